// round 7
// baseline (speedup 1.0000x reference)
#include <cuda_runtime.h>
#include <cuda_bf16.h>

#define N_LEVELS 20
#define LOG2T 19
#define TSIZE (1 << LOG2T)
#define TMASK (TSIZE - 1)
#define PRIME_Y 2654435761u
#define PRIME_Z 805459861u

#define CAP       (1 << 20)     // max points supported by sort path
#define KEY_BITS  5             // per-dim
#define GRID_DIM  (1 << KEY_BITS)
#define NBUCKETS  (1 << (3 * KEY_BITS))   // 32768

// Static scratch (no allocation allowed).
__device__ float4   g_scratch[CAP];
__device__ int      g_keys[CAP];
__device__ int      g_rank[CAP];
__device__ unsigned g_hist[NBUCKETS];
__device__ unsigned g_base[NBUCKETS];

// res[i] = int(16 * 1.39**i); verified against double-precision pow.
__constant__ float c_res[N_LEVELS] = {
    16.f, 22.f, 30.f, 42.f, 59.f, 83.f, 115.f, 160.f, 222.f, 309.f,
    430.f, 598.f, 832.f, 1156.f, 1608.f, 2235.f, 3107.f, 4318.f, 6003.f, 8344.f
};

__device__ __forceinline__ int bucket_key(float px, float py, float pz)
{
    int ix = min(GRID_DIM - 1, (int)(px * (float)GRID_DIM));
    int iy = min(GRID_DIM - 1, (int)(py * (float)GRID_DIM));
    int iz = min(GRID_DIM - 1, (int)(pz * (float)GRID_DIM));
    return (ix << (2 * KEY_BITS)) | (iy << KEY_BITS) | iz;
}

// ---------------- sort pipeline ----------------

__global__ void zero_hist_kernel()
{
    int i = blockIdx.x * blockDim.x + threadIdx.x;
    if (i < NBUCKETS) g_hist[i] = 0u;
}

// 2 points per thread. atomicAdd's return value IS the point's rank within
// its bucket -> scatter needs no atomics at all.
__global__ void hist_kernel(const float* __restrict__ x, int n)
{
    int t = blockIdx.x * blockDim.x + threadIdx.x;
    int p0 = 2 * t;
    int p1 = p0 + 1;
    if (p0 >= n) return;

    int k0 = bucket_key(x[3 * p0], x[3 * p0 + 1], x[3 * p0 + 2]);
    if (p1 < n) {
        int k1 = bucket_key(x[3 * p1], x[3 * p1 + 1], x[3 * p1 + 2]);
        g_keys[p1] = k1;
        unsigned r1 = atomicAdd(&g_hist[k1], 1u);
        g_rank[p1] = (int)r1;
    }
    g_keys[p0] = k0;
    unsigned r0 = atomicAdd(&g_hist[k0], 1u);
    g_rank[p0] = (int)r0;
}

// One block, 1024 threads; each thread owns 32 consecutive buckets.
// Writes exclusive bucket start offsets into g_base.
__global__ void __launch_bounds__(1024)
prefix_kernel()
{
    __shared__ unsigned part[1024];
    int t = threadIdx.x;

    unsigned local[NBUCKETS / 1024];
    unsigned s = 0;
#pragma unroll
    for (int j = 0; j < NBUCKETS / 1024; ++j) {
        local[j] = g_hist[t * (NBUCKETS / 1024) + j];
        s += local[j];
    }
    part[t] = s;
    __syncthreads();

    for (int off = 1; off < 1024; off <<= 1) {
        unsigned v = (t >= off) ? part[t - off] : 0u;
        __syncthreads();
        part[t] += v;
        __syncthreads();
    }

    unsigned run = (t > 0) ? part[t - 1] : 0u;
#pragma unroll
    for (int j = 0; j < NBUCKETS / 1024; ++j) {
        g_base[t * (NBUCKETS / 1024) + j] = run;
        run += local[j];
    }
}

// Atomic-free scatter: pos = base[key] + rank. Pure bandwidth.
__global__ void scatter_kernel(const float* __restrict__ x, int n)
{
    int t = blockIdx.x * blockDim.x + threadIdx.x;
    int p0 = 2 * t;
    int p1 = p0 + 1;
    if (p0 >= n) return;

    unsigned pos0 = g_base[g_keys[p0]] + (unsigned)g_rank[p0];
    float a0 = x[3 * p0], b0 = x[3 * p0 + 1], c0 = x[3 * p0 + 2];
    if (p1 < n) {
        unsigned pos1 = g_base[g_keys[p1]] + (unsigned)g_rank[p1];
        float a1 = x[3 * p1], b1 = x[3 * p1 + 1], c1 = x[3 * p1 + 2];
        g_scratch[pos1] = make_float4(a1, b1, c1, __int_as_float(p1));
    }
    g_scratch[pos0] = make_float4(a0, b0, c0, __int_as_float(p0));
}

// ---------------- encode ----------------

// Paired-corner trick: hash(vx,y,z) = vx ^ s, so the 16B-aligned table pair
// {i&~1, i|1} holds entries for x-coords {vx, vx^1}. Even vx: that is
// (vx, vx+1) -> one LDG.128 serves both corners. Odd vx: a predicated second
// load fetches vx+1.
__device__ __forceinline__ float2 encode_level(float px, float py, float pz,
                                               const float2* __restrict__ tab,
                                               float res)
{
    const float4* __restrict__ tab4 = reinterpret_cast<const float4*>(tab);

    float xs = px * res, ys = py * res, zs = pz * res;
    float fx = floorf(xs), fy = floorf(ys), fz = floorf(zs);
    float wx = xs - fx, wy = ys - fy, wz = zs - fz;

    unsigned vx = (unsigned)(int)fx;
    unsigned vy = (unsigned)(int)fy;
    unsigned vz = (unsigned)(int)fz;

    unsigned hy0 = vy * PRIME_Y;
    unsigned hy1 = (vy + 1u) * PRIME_Y;
    unsigned hz0 = vz * PRIME_Z;
    unsigned hz1 = (vz + 1u) * PRIME_Z;

    unsigned s00 = hy0 ^ hz0;
    unsigned s01 = hy0 ^ hz1;
    unsigned s10 = hy1 ^ hz0;
    unsigned s11 = hy1 ^ hz1;

    unsigned vx1 = vx + 1u;
    bool odd = (vx & 1u) != 0u;

    unsigned i00 = (vx ^ s00) & TMASK;
    unsigned i01 = (vx ^ s01) & TMASK;
    unsigned i10 = (vx ^ s10) & TMASK;
    unsigned i11 = (vx ^ s11) & TMASK;

    float4 q00 = __ldg(&tab4[i00 >> 1]);
    float4 q01 = __ldg(&tab4[i01 >> 1]);
    float4 q10 = __ldg(&tab4[i10 >> 1]);
    float4 q11 = __ldg(&tab4[i11 >> 1]);

    // Predicated extra loads: only odd-vx lanes touch memory.
    float2 g00 = make_float2(0.f, 0.f);
    float2 g01 = g00, g10 = g00, g11 = g00;
    if (odd) {
        g00 = __ldg(&tab[(vx1 ^ s00) & TMASK]);
        g01 = __ldg(&tab[(vx1 ^ s01) & TMASK]);
        g10 = __ldg(&tab[(vx1 ^ s10) & TMASK]);
        g11 = __ldg(&tab[(vx1 ^ s11) & TMASK]);
    }

    float2 lo00 = make_float2(q00.x, q00.y), hi00 = make_float2(q00.z, q00.w);
    float2 lo01 = make_float2(q01.x, q01.y), hi01 = make_float2(q01.z, q01.w);
    float2 lo10 = make_float2(q10.x, q10.y), hi10 = make_float2(q10.z, q10.w);
    float2 lo11 = make_float2(q11.x, q11.y), hi11 = make_float2(q11.z, q11.w);

    bool p00 = (i00 & 1u) != 0u;
    bool p01 = (i01 & 1u) != 0u;
    bool p10 = (i10 & 1u) != 0u;
    bool p11 = (i11 & 1u) != 0u;

    float2 e0 = p00 ? hi00 : lo00;
    float2 e1 = p01 ? hi01 : lo01;
    float2 e2 = p10 ? hi10 : lo10;
    float2 e3 = p11 ? hi11 : lo11;

    float2 n00 = p00 ? lo00 : hi00;
    float2 n01 = p01 ? lo01 : hi01;
    float2 n10 = p10 ? lo10 : hi10;
    float2 n11 = p11 ? lo11 : hi11;

    float2 e4 = odd ? g00 : n00;
    float2 e5 = odd ? g01 : n01;
    float2 e6 = odd ? g10 : n10;
    float2 e7 = odd ? g11 : n11;

    float omx = 1.f - wx, omy = 1.f - wy, omz = 1.f - wz;

    float c00a = e0.x * omx + e4.x * wx;
    float c01a = e1.x * omx + e5.x * wx;
    float c10a = e2.x * omx + e6.x * wx;
    float c11a = e3.x * omx + e7.x * wx;
    float c0a  = c00a * omy + c10a * wy;
    float c1a  = c01a * omy + c11a * wy;
    float ra   = c0a * omz + c1a * wz;

    float c00b = e0.y * omx + e4.y * wx;
    float c01b = e1.y * omx + e5.y * wx;
    float c10b = e2.y * omx + e6.y * wx;
    float c11b = e3.y * omx + e7.y * wx;
    float c0b  = c00b * omy + c10b * wy;
    float c1b  = c01b * omy + c11b * wy;
    float rb   = c0b * omz + c1b * wz;

    return make_float2(ra, rb);
}

__device__ __forceinline__ void encode_point(float px, float py, float pz,
                                             const float* __restrict__ tables,
                                             float4* __restrict__ out4)
{
#pragma unroll
    for (int l = 0; l < N_LEVELS; l += 4) {
        const float2* __restrict__ t0 =
            reinterpret_cast<const float2*>(tables) + (size_t)l * TSIZE;
        const float2* __restrict__ t1 = t0 + TSIZE;
        const float2* __restrict__ t2 = t1 + TSIZE;
        const float2* __restrict__ t3 = t2 + TSIZE;

        float2 r0 = encode_level(px, py, pz, t0, c_res[l]);
        float2 r1 = encode_level(px, py, pz, t1, c_res[l + 1]);
        float2 r2 = encode_level(px, py, pz, t2, c_res[l + 2]);
        float2 r3 = encode_level(px, py, pz, t3, c_res[l + 3]);

        __stcs(&out4[(l >> 1)],     make_float4(r0.x, r0.y, r1.x, r1.y));
        __stcs(&out4[(l >> 1) + 1], make_float4(r2.x, r2.y, r3.x, r3.y));
    }
}

__global__ void __launch_bounds__(256)
encode_sorted_kernel(const float* __restrict__ tables,
                     float* __restrict__ out,
                     int n)
{
    int i = blockIdx.x * blockDim.x + threadIdx.x;
    if (i >= n) return;

    float4 s = g_scratch[i];
    int id = __float_as_int(s.w);
    float4* __restrict__ out4 =
        reinterpret_cast<float4*>(out) + (size_t)id * (N_LEVELS / 2);

    encode_point(s.x, s.y, s.z, tables, out4);
}

// Fallback (n > CAP): encode directly from x in input order.
__global__ void __launch_bounds__(256)
encode_direct_kernel(const float* __restrict__ x,
                     const float* __restrict__ tables,
                     float* __restrict__ out,
                     int n)
{
    int p = blockIdx.x * blockDim.x + threadIdx.x;
    if (p >= n) return;

    float4* __restrict__ out4 =
        reinterpret_cast<float4*>(out) + (size_t)p * (N_LEVELS / 2);
    encode_point(x[3 * p], x[3 * p + 1], x[3 * p + 2], tables, out4);
}

extern "C" void kernel_launch(void* const* d_in, const int* in_sizes, int n_in,
                              void* d_out, int out_size)
{
    const float* x      = (const float*)d_in[0];
    const float* tables = (const float*)d_in[1];
    float* out          = (float*)d_out;

    int n = in_sizes[0] / 3;
    int threads = 256;
    int blocks = (n + threads - 1) / threads;
    int blocks2 = (n / 2 + threads) / threads;   // 2 points per thread

    if (n <= CAP) {
        zero_hist_kernel<<<(NBUCKETS + 1023) / 1024, 1024>>>();
        hist_kernel<<<blocks2, threads>>>(x, n);
        prefix_kernel<<<1, 1024>>>();
        scatter_kernel<<<blocks2, threads>>>(x, n);
        encode_sorted_kernel<<<blocks, threads>>>(tables, out, n);
    } else {
        encode_direct_kernel<<<blocks, threads>>>(x, tables, out, n);
    }
}